// round 13
// baseline (speedup 1.0000x reference)
#include <cuda_runtime.h>
#include <cuda_bf16.h>
#include <math.h>
#include <stdint.h>

#define G 64
#define NN 1000
#define EE 8192
#define C 128
#define HIDN 256
#define NCLS 2

// ---------------- scratch (device globals; no allocation allowed) ----------------
__device__ float g_bufA[(size_t)G * NN * C];   // 32.8 MB
__device__ float g_bufB[(size_t)G * NN * C];   // 32.8 MB
__device__ float g_dinv[G * NN];
__device__ int   g_rowptr[G * (NN + 1)];
__device__ float2 g_edge[G * EE];              // {src_as_float, dinv[src]*dinv[dst]}
__device__ float g_gvec[G * C];
__device__ float g_qkv[G * 3 * C];
__device__ float g_nrepr[C];
// W fragments (bf16 big/small pairs) per-thread MMA layout:
// [layer][coltile*256 + q*32 + lane] -> float4 of 4 x (bf16x2)
__device__ float4 g_wfB[2][2048];
__device__ float4 g_wfS[2][2048];

// ---------------- bf16 helpers ----------------
__device__ __forceinline__ uint32_t pack2bf(float lo, float hi) {
    uint32_t u;
    asm("cvt.rn.bf16x2.f32 %0, %1, %2;" : "=r"(u) : "f"(hi), "f"(lo));  // d[31:16]=hi, d[15:0]=lo
    return u;
}
__device__ __forceinline__ float bfbits2f(uint32_t bits16) {
    return __uint_as_float(bits16 << 16);
}
__device__ __forceinline__ void split2bf(float lo, float hi, uint32_t& big, uint32_t& small) {
    big = pack2bf(lo, hi);
    float rlo = lo - bfbits2f(big & 0xffffu);
    float rhi = hi - bfbits2f(big >> 16);
    small = pack2bf(rlo, rhi);
}

#define MMA_BF16(D,a0,a1,a2,a3,b0,b1)                                        \
    asm volatile(                                                            \
        "mma.sync.aligned.m16n8k16.row.col.f32.bf16.bf16.f32 "               \
        "{%0,%1,%2,%3}, {%4,%5,%6,%7}, {%8,%9}, {%0,%1,%2,%3};\n"            \
        : "+f"(D[0]), "+f"(D[1]), "+f"(D[2]), "+f"(D[3])                     \
        : "r"(a0), "r"(a1), "r"(a2), "r"(a3), "r"(b0), "r"(b1))

// ---------------- fused graph prep (+ W fragment precompute in blocks 0-3) ----------------
__global__ void prep_kernel(const int* __restrict__ ei,
                            const float* __restrict__ W0, const float* __restrict__ W1) {
    __shared__ int cnt[1024];
    __shared__ int cur[NN];
    __shared__ float sdinv[NN];
    __shared__ int wtot[32];
    int g = blockIdx.x;
    int t = threadIdx.x;          // 1024 threads
    int warp = t >> 5, lane = t & 31;
    const int* eb = ei + (size_t)g * 2 * EE;

    // ---- W fragments: 2 layers x 2048 items, blocks 0-3 ----
    if (g < 4) {
        int idx = g * 1024 + t;             // 0..4095
        int layer = idx >> 11;
        int id2 = idx & 2047;
        const float* W = layer ? W1 : W0;
        int lane2 = id2 & 31;
        int q = (id2 >> 5) & 7;             // k16 chunk
        int ct = id2 >> 8;                  // 16-col tile
        int grp = lane2 >> 2, tig = lane2 & 3;
        int k0 = q * 16 + 2 * tig;
        int m0 = ct * 16 + grp;
        uint32_t b[4], s[4];
        split2bf(W[k0 * 128 + m0],       W[(k0 + 1) * 128 + m0],       b[0], s[0]);
        split2bf(W[k0 * 128 + m0 + 8],   W[(k0 + 1) * 128 + m0 + 8],   b[1], s[1]);
        split2bf(W[(k0 + 8) * 128 + m0], W[(k0 + 9) * 128 + m0],       b[2], s[2]);
        split2bf(W[(k0 + 8) * 128 + m0 + 8], W[(k0 + 9) * 128 + m0 + 8], b[3], s[3]);
        g_wfB[layer][id2] = make_float4(__uint_as_float(b[0]), __uint_as_float(b[1]),
                                        __uint_as_float(b[2]), __uint_as_float(b[3]));
        g_wfS[layer][id2] = make_float4(__uint_as_float(s[0]), __uint_as_float(s[1]),
                                        __uint_as_float(s[2]), __uint_as_float(s[3]));
    }

    cnt[t] = 0;
    __syncthreads();
    for (int e = t; e < EE; e += 1024) atomicAdd(&cnt[eb[EE + e]], 1);
    __syncthreads();
    int d = cnt[t];

    int v = d;
#pragma unroll
    for (int off = 1; off < 32; off <<= 1) {
        int u = __shfl_up_sync(0xffffffffu, v, off);
        if (lane >= off) v += u;
    }
    if (lane == 31) wtot[warp] = v;
    __syncthreads();
    if (warp == 0) {
        int wv = wtot[lane];
#pragma unroll
        for (int off = 1; off < 32; off <<= 1) {
            int u = __shfl_up_sync(0xffffffffu, wv, off);
            if (lane >= off) wv += u;
        }
        wtot[lane] = wv;
    }
    __syncthreads();
    int incl = v + (warp > 0 ? wtot[warp - 1] : 0);

    if (t < NN) {
        g_rowptr[g * (NN + 1) + t + 1] = incl;
        cur[t] = incl - d;
        float di = rsqrtf((float)d + 1.0f);
        sdinv[t] = di;
        g_dinv[g * NN + t] = di;
    }
    if (t == 0) g_rowptr[g * (NN + 1)] = 0;
    if (t < C) g_gvec[g * C + t] = 0.0f;
    if (g == 0 && t < C) g_nrepr[t] = 0.0f;
    __syncthreads();
    for (int e = t; e < EE; e += 1024) {
        int src = eb[e];
        int dst = eb[EE + e];
        int pos = atomicAdd(&cur[dst], 1);
        g_edge[g * EE + pos] = make_float2(__int_as_float(src), sdinv[src] * sdinv[dst]);
    }
}

// ---------------- bf16x3 tensor-core GEMM: (64000 x 128) @ (128 x 128) ----------------
// X packed per (row, q, slot): float4 {blo(pair tig), slo(pair tig), bhi(pair tig+4), shi(pair tig+4)}
// Row stride 36 float4 (144 words). Slot swizzle (tig + (q>>1)) & 3.
// Staging: lane = float4-column (coalesced LDG.128), each thread emits 2 pairs as STS.64.
// Epilogue: D staged in smem (stride 132 floats, conflict-free) -> coalesced STG.128.
#define XROW_F4 36
#define DROW_F 132
#define GEMM_SMEM_BYTES (64 * XROW_F4 * 16)   // 36864 >= 64*132*4 = 33792

__global__ void __launch_bounds__(256, 3)
gemm_tc_kernel(const float* __restrict__ X,
               const float4* __restrict__ WfB, const float4* __restrict__ WfS,
               float* __restrict__ Y) {
    extern __shared__ uint32_t usm[];
    float4* Xq4 = (float4*)usm;

    int tid = threadIdx.x;
    int warp = tid >> 5, lane = tid & 31;
    int rowBase = blockIdx.x * 64;

    // ---- staging: lane = c4 (coalesced LDG.128), pair-local STS.64 (conflict-free)
    {
        int c4 = lane;                   // float4 column 0..31
        int q = c4 >> 2;                 // k16 chunk
        int l2 = c4 & 3;                 // pair group: pairs 2*l2, 2*l2+1 of chunk q
#pragma unroll
        for (int it = 0; it < 8; it++) {
            int r = it * 8 + warp;
            float4 v = ((const float4*)(X + (size_t)(rowBase + r) * C))[c4];
            // pair t0 = 2*l2: floats (v.x, v.y); pair t0+1: (v.z, v.w)
#pragma unroll
            for (int p = 0; p < 2; p++) {
                int tt = 2 * l2 + p;
                int tg = tt & 3;
                int comp = tt >> 2;                       // 0: words {0,1}, 1: words {2,3}
                int slot = (tg + (q >> 1)) & 3;
                uint32_t big, small;
                if (p == 0) split2bf(v.x, v.y, big, small);
                else        split2bf(v.z, v.w, big, small);
                uint32_t* w = usm + r * (XROW_F4 * 4) + q * 16 + slot * 4 + comp * 2;
                *(uint2*)w = make_uint2(big, small);      // STS.64
            }
        }
    }
    __syncthreads();

    int grp = lane >> 2, tig = lane & 3;
    int wN = warp & 3, wM = warp >> 2;      // 4 N-groups x 2 M-groups
    int ct0 = wN * 2;                       // two 16-col tiles per warp
    int rbase = wM * 32;                    // 32 rows per warp (4 rt of 8)

    float d[2][4][4];
#pragma unroll
    for (int a = 0; a < 2; a++)
#pragma unroll
        for (int b = 0; b < 4; b++)
#pragma unroll
            for (int c = 0; c < 4; c++) d[a][b][c] = 0.0f;

    const float4* wb0 = WfB + ct0 * 256 + lane;
    const float4* ws0 = WfS + ct0 * 256 + lane;
    const float4* wb1 = WfB + (ct0 + 1) * 256 + lane;
    const float4* ws1 = WfS + (ct0 + 1) * 256 + lane;

#pragma unroll
    for (int q = 0; q < 8; q++) {
        float4 A0 = __ldg(wb0 + q * 32);
        float4 S0 = __ldg(ws0 + q * 32);
        float4 A1 = __ldg(wb1 + q * 32);
        float4 S1 = __ldg(ws1 + q * 32);
        uint32_t a00 = __float_as_uint(A0.x), a01 = __float_as_uint(A0.y),
                 a02 = __float_as_uint(A0.z), a03 = __float_as_uint(A0.w);
        uint32_t s00 = __float_as_uint(S0.x), s01 = __float_as_uint(S0.y),
                 s02 = __float_as_uint(S0.z), s03 = __float_as_uint(S0.w);
        uint32_t a10 = __float_as_uint(A1.x), a11 = __float_as_uint(A1.y),
                 a12 = __float_as_uint(A1.z), a13 = __float_as_uint(A1.w);
        uint32_t s10 = __float_as_uint(S1.x), s11 = __float_as_uint(S1.y),
                 s12 = __float_as_uint(S1.z), s13 = __float_as_uint(S1.w);
        int slot = (tig + (q >> 1)) & 3;
#pragma unroll
        for (int rt = 0; rt < 4; rt++) {
            float4 xq = Xq4[(rbase + rt * 8 + grp) * XROW_F4 + q * 4 + slot];
            // layout {blo, slo, bhi, shi}: big = (x, z), small = (y, w)
            uint32_t bb0 = __float_as_uint(xq.x), bb1 = __float_as_uint(xq.z);
            uint32_t bs0 = __float_as_uint(xq.y), bs1 = __float_as_uint(xq.w);
            MMA_BF16(d[0][rt], a00, a01, a02, a03, bb0, bb1);
            MMA_BF16(d[0][rt], s00, s01, s02, s03, bb0, bb1);
            MMA_BF16(d[0][rt], a00, a01, a02, a03, bs0, bs1);
            MMA_BF16(d[1][rt], a10, a11, a12, a13, bb0, bb1);
            MMA_BF16(d[1][rt], s10, s11, s12, s13, bb0, bb1);
            MMA_BF16(d[1][rt], a10, a11, a12, a13, bs0, bs1);
        }
    }

    // ---- epilogue: stage D in smem (conflict-free STS.32), then coalesced STG.128
    __syncthreads();                       // X data no longer needed
    float* Ds = (float*)usm;               // [64][132]
#pragma unroll
    for (int ct = 0; ct < 2; ct++) {
        int cc = (ct0 + ct) * 16 + grp;
#pragma unroll
        for (int rt = 0; rt < 4; rt++) {
            int r0 = rbase + rt * 8 + 2 * tig;
            Ds[r0 * DROW_F + cc]           = d[ct][rt][0];
            Ds[(r0 + 1) * DROW_F + cc]     = d[ct][rt][1];
            Ds[r0 * DROW_F + cc + 8]       = d[ct][rt][2];
            Ds[(r0 + 1) * DROW_F + cc + 8] = d[ct][rt][3];
        }
    }
    __syncthreads();
    for (int i = tid; i < 64 * 32; i += 256) {
        int r = i >> 5, c4 = i & 31;
        float4 v = *(const float4*)(Ds + r * DROW_F + c4 * 4);
        ((float4*)(Y + (size_t)(rowBase + r) * C))[c4] = v;
    }
}

// ---------------- aggregation: warp per node, lane = 4 cols, packed edges ----------------
__device__ __forceinline__ float fast_tanh(float x) {
    float r;
    asm("tanh.approx.f32 %0, %1;" : "=f"(r) : "f"(x));
    return r;
}

template <int LAYER>
__global__ void __launch_bounds__(256)
agg_kernel(const float* __restrict__ h, float* __restrict__ out,
           const float* __restrict__ bias) {
    int g = blockIdx.y;
    int warp = threadIdx.x >> 5, lane = threadIdx.x & 31;
    int n = blockIdx.x * 8 + warp;      // 0..999
    int col = lane * 4;

    const float* hb = h + (size_t)g * NN * C + col;
    const float2* ep = g_edge + g * EE;
    int st = __ldg(&g_rowptr[g * (NN + 1) + n]);
    int en = __ldg(&g_rowptr[g * (NN + 1) + n + 1]);
    float dn = __ldg(&g_dinv[g * NN + n]);
    float4 bia = *(const float4*)(bias + col);

    float4 self = *(const float4*)(hb + (size_t)n * C);
    float d2 = dn * dn;
    float4 acc;
    acc.x = self.x * d2 + bia.x;
    acc.y = self.y * d2 + bia.y;
    acc.z = self.z * d2 + bia.z;
    acc.w = self.w * d2 + bia.w;

    for (int e = st; e < en; e++) {
        float2 eg = __ldg(&ep[e]);
        int s = __float_as_int(eg.x);
        float w = eg.y;
        float4 hr = *(const float4*)(hb + (size_t)s * C);
        acc.x += hr.x * w;
        acc.y += hr.y * w;
        acc.z += hr.z * w;
        acc.w += hr.w * w;
    }
    acc.x = fast_tanh(acc.x);
    acc.y = fast_tanh(acc.y);
    acc.z = fast_tanh(acc.z);
    acc.w = fast_tanh(acc.w);

    if (LAYER == 0) {
        *(float4*)(out + ((size_t)g * NN + n) * C + col) = acc;
    } else {
        __shared__ float4 wsum[8][32];
        wsum[warp][lane] = acc;
        __syncthreads();
        if (warp == 0) {
            float4 s = wsum[0][lane];
#pragma unroll
            for (int w = 1; w < 8; w++) {
                float4 t = wsum[w][lane];
                s.x += t.x; s.y += t.y; s.z += t.z; s.w += t.w;
            }
            atomicAdd(&g_gvec[g * C + col], s.x);
            atomicAdd(&g_gvec[g * C + col + 1], s.y);
            atomicAdd(&g_gvec[g * C + col + 2], s.z);
            atomicAdd(&g_gvec[g * C + col + 3], s.w);
        }
    }
}

// ---------------- qkv: one block per graph-row ----------------
__global__ void qkv_kernel(const float* __restrict__ in_w, const float* __restrict__ in_b) {
    int bi = blockIdx.x;
    int tid = threadIdx.x;       // 384 threads
    __shared__ float gr[C];
    if (tid < C) gr[tid] = g_gvec[bi * C + tid];
    __syncthreads();
    float acc = in_b[tid];
    const float* wr = in_w + (size_t)tid * C;
#pragma unroll 4
    for (int c = 0; c < C; c++) acc += gr[c] * wr[c];
    g_qkv[bi * 3 * C + tid] = acc;
}

// ---------------- attention + out-proj + MLP + LN + relu-sum ----------------
__device__ __forceinline__ float blksum128(float v, float* red) {
#pragma unroll
    for (int o = 16; o > 0; o >>= 1) v += __shfl_down_sync(0xffffffffu, v, o);
    if ((threadIdx.x & 31) == 0) red[threadIdx.x >> 5] = v;
    __syncthreads();
    float s = red[0] + red[1] + red[2] + red[3];
    __syncthreads();
    return s;
}

__global__ void tail_kernel(const float* __restrict__ out_w, const float* __restrict__ out_b,
                            const float* __restrict__ ln_g, const float* __restrict__ ln_b,
                            const float* __restrict__ mw1, const float* __restrict__ mb1,
                            const float* __restrict__ mw2, const float* __restrict__ mb2) {
    int bi = blockIdx.x;
    int tid = threadIdx.x;       // 128 threads
    __shared__ float kv[64 * C];
    __shared__ float qrow[C], sc[4 * 64], orow[C], o2row[C], hid[HIDN];
    __shared__ float red[4];

    for (int i = tid; i < 64 * C; i += 128) {
        int r = i >> 7, c = i & 127;
        kv[i] = g_qkv[r * 3 * C + C + c];
    }
    qrow[tid] = g_qkv[bi * 3 * C + tid];
    __syncthreads();

    for (int s = tid; s < 256; s += 128) {
        int h = s >> 6, k = s & 63;
        const float* kr = kv + k * C + h * 32;
        const float* qr = qrow + h * 32;
        float a = 0.f;
#pragma unroll
        for (int dd = 0; dd < 32; dd++) a += qr[dd] * kr[dd];
        sc[s] = a * 0.17677669529663687f;
    }
    __syncthreads();

    if (tid < 4) {
        float m = -1e30f;
        for (int k = 0; k < 64; k++) m = fmaxf(m, sc[tid * 64 + k]);
        float ssum = 0.f;
        for (int k = 0; k < 64; k++) { float e = expf(sc[tid * 64 + k] - m); sc[tid * 64 + k] = e; ssum += e; }
        float inv = 1.0f / ssum;
        for (int k = 0; k < 64; k++) sc[tid * 64 + k] *= inv;
    }
    __syncthreads();

    for (int i = tid; i < 64 * C; i += 128) {
        int r = i >> 7, c = i & 127;
        kv[i] = g_qkv[r * 3 * C + 2 * C + c];
    }
    __syncthreads();

    {
        int c = tid, h = c >> 5;
        float a = 0.f;
        for (int k = 0; k < 64; k++) a += sc[h * 64 + k] * kv[k * C + c];
        orow[c] = a;
    }
    __syncthreads();

    {
        int j = tid;
        float a = out_b[j];
        const float* wr = out_w + (size_t)j * C;
#pragma unroll 4
        for (int c = 0; c < C; c++) a += orow[c] * wr[c];
        o2row[j] = a;
    }
    __syncthreads();

    for (int j = tid; j < HIDN; j += 128) {
        float a = mb1[j];
        for (int c = 0; c < C; c++) a += o2row[c] * mw1[c * HIDN + j];
        hid[j] = fmaxf(a, 0.f);
    }
    __syncthreads();

    float y;
    {
        int c = tid;
        float a = mb2[c];
        for (int j = 0; j < HIDN; j++) a += hid[j] * mw2[j * C + c];
        y = o2row[c] + a;
    }
    float mu = blksum128(y, red) * (1.0f / 128.0f);
    float d = y - mu;
    float var = blksum128(d * d, red) * (1.0f / 128.0f);
    float yn = d * rsqrtf(var + 1e-5f) * ln_g[tid] + ln_b[tid];
    atomicAdd(&g_nrepr[tid], fmaxf(yn, 0.f));
}

__global__ void final_kernel(const float* __restrict__ lw, const float* __restrict__ lb,
                             float* __restrict__ out) {
    int tid = threadIdx.x;
    if (tid < NCLS) {
        float a = lb[tid];
        for (int c = 0; c < C; c++) a += g_nrepr[c] * lw[c * NCLS + tid];
        out[tid] = a;
    }
}

// ---------------- launch ----------------
extern "C" void kernel_launch(void* const* d_in, const int* in_sizes, int n_in,
                              void* d_out, int out_size) {
    const float* x     = (const float*)d_in[0];
    const int*   ei    = (const int*)d_in[1];
    const float* W0    = (const float*)d_in[2];
    const float* b0    = (const float*)d_in[3];
    const float* W1    = (const float*)d_in[4];
    const float* b1    = (const float*)d_in[5];
    const float* in_w  = (const float*)d_in[6];
    const float* in_b  = (const float*)d_in[7];
    const float* out_w = (const float*)d_in[8];
    const float* out_b = (const float*)d_in[9];
    const float* ln2_g = (const float*)d_in[10];
    const float* ln2_b = (const float*)d_in[11];
    const float* mw1   = (const float*)d_in[12];
    const float* mb1   = (const float*)d_in[13];
    const float* mw2   = (const float*)d_in[14];
    const float* mb2   = (const float*)d_in[15];
    const float* lw    = (const float*)d_in[16];
    const float* lb    = (const float*)d_in[17];
    float* out = (float*)d_out;

    float *bufA, *bufB;
    cudaGetSymbolAddress((void**)&bufA, g_bufA);
    cudaGetSymbolAddress((void**)&bufB, g_bufB);
    float4 *wfB, *wfS;
    cudaGetSymbolAddress((void**)&wfB, g_wfB);
    cudaGetSymbolAddress((void**)&wfS, g_wfS);

    cudaFuncSetAttribute(gemm_tc_kernel, cudaFuncAttributeMaxDynamicSharedMemorySize, GEMM_SMEM_BYTES);

    prep_kernel<<<G, 1024>>>(ei, W0, W1);

    gemm_tc_kernel<<<(G * NN) / 64, 256, GEMM_SMEM_BYTES>>>(x, wfB, wfS, bufA);
    agg_kernel<0><<<dim3(125, G), 256>>>(bufA, bufB, b0);
    gemm_tc_kernel<<<(G * NN) / 64, 256, GEMM_SMEM_BYTES>>>(bufB, wfB + 2048, wfS + 2048, bufA);
    agg_kernel<1><<<dim3(125, G), 256>>>(bufA, nullptr, b1);

    qkv_kernel<<<G, 3 * C>>>(in_w, in_b);
    tail_kernel<<<G, C>>>(out_w, out_b, ln2_g, ln2_b, mw1, mb1, mw2, mb2);
    final_kernel<<<1, 32>>>(lw, lb, out);
}

// round 15
// speedup vs baseline: 1.0515x; 1.0515x over previous
#include <cuda_runtime.h>
#include <cuda_bf16.h>
#include <cuda_fp16.h>
#include <math.h>
#include <stdint.h>

#define G 64
#define NN 1000
#define EE 8192
#define C 128
#define HIDN 256
#define NCLS 2

// ---------------- scratch (device globals; no allocation allowed) ----------------
__device__ __half g_bufA[(size_t)G * NN * C];  // 16.4 MB (gemm outputs fp16, agg gather src)
__device__ float g_bufB[(size_t)G * NN * C];   // 32.8 MB (tanh outputs fp32, gemm2 input)
__device__ float g_dinv[G * NN];
__device__ int   g_rowptr[G * (NN + 1)];
__device__ float2 g_edge[G * EE];              // {src_as_float, dinv[src]*dinv[dst]}
__device__ float g_gvec[G * C];
__device__ float g_qkv[G * 3 * C];
__device__ float g_nrepr[C];
// W fragments (bf16 big/small pairs) per-thread MMA layout:
// [layer][coltile*256 + q*32 + lane] -> float4 of 4 x (bf16x2)
__device__ float4 g_wfB[2][2048];
__device__ float4 g_wfS[2][2048];

// ---------------- bf16 / fp16 helpers ----------------
__device__ __forceinline__ uint32_t pack2bf(float lo, float hi) {
    uint32_t u;
    asm("cvt.rn.bf16x2.f32 %0, %1, %2;" : "=r"(u) : "f"(hi), "f"(lo));  // d[31:16]=hi, d[15:0]=lo
    return u;
}
__device__ __forceinline__ float bfbits2f(uint32_t bits16) {
    return __uint_as_float(bits16 << 16);
}
__device__ __forceinline__ void split2bf(float lo, float hi, uint32_t& big, uint32_t& small) {
    big = pack2bf(lo, hi);
    float rlo = lo - bfbits2f(big & 0xffffu);
    float rhi = hi - bfbits2f(big >> 16);
    small = pack2bf(rlo, rhi);
}
__device__ __forceinline__ uint32_t pack2h(float lo, float hi) {
    uint32_t u;
    asm("cvt.rn.f16x2.f32 %0, %1, %2;" : "=r"(u) : "f"(hi), "f"(lo));   // d[31:16]=hi, d[15:0]=lo
    return u;
}
__device__ __forceinline__ float4 unpack4h(uint2 u) {
    __half2 a = *reinterpret_cast<__half2*>(&u.x);
    __half2 b = *reinterpret_cast<__half2*>(&u.y);
    float2 fa = __half22float2(a), fb = __half22float2(b);
    return make_float4(fa.x, fa.y, fb.x, fb.y);
}

#define MMA_BF16(D,a0,a1,a2,a3,b0,b1)                                        \
    asm volatile(                                                            \
        "mma.sync.aligned.m16n8k16.row.col.f32.bf16.bf16.f32 "               \
        "{%0,%1,%2,%3}, {%4,%5,%6,%7}, {%8,%9}, {%0,%1,%2,%3};\n"            \
        : "+f"(D[0]), "+f"(D[1]), "+f"(D[2]), "+f"(D[3])                     \
        : "r"(a0), "r"(a1), "r"(a2), "r"(a3), "r"(b0), "r"(b1))

// ---------------- fused graph prep (+ W fragment precompute in blocks 0-3) ----------------
__global__ void prep_kernel(const int* __restrict__ ei,
                            const float* __restrict__ W0, const float* __restrict__ W1) {
    __shared__ int cnt[1024];
    __shared__ int cur[NN];
    __shared__ float sdinv[NN];
    __shared__ int wtot[32];
    int g = blockIdx.x;
    int t = threadIdx.x;          // 1024 threads
    int warp = t >> 5, lane = t & 31;
    const int* eb = ei + (size_t)g * 2 * EE;

    // ---- W fragments: 2 layers x 2048 items, blocks 0-3 ----
    if (g < 4) {
        int idx = g * 1024 + t;             // 0..4095
        int layer = idx >> 11;
        int id2 = idx & 2047;
        const float* W = layer ? W1 : W0;
        int lane2 = id2 & 31;
        int q = (id2 >> 5) & 7;             // k16 chunk
        int ct = id2 >> 8;                  // 16-col tile
        int grp = lane2 >> 2, tig = lane2 & 3;
        int k0 = q * 16 + 2 * tig;
        int m0 = ct * 16 + grp;
        uint32_t b[4], s[4];
        split2bf(W[k0 * 128 + m0],       W[(k0 + 1) * 128 + m0],       b[0], s[0]);
        split2bf(W[k0 * 128 + m0 + 8],   W[(k0 + 1) * 128 + m0 + 8],   b[1], s[1]);
        split2bf(W[(k0 + 8) * 128 + m0], W[(k0 + 9) * 128 + m0],       b[2], s[2]);
        split2bf(W[(k0 + 8) * 128 + m0 + 8], W[(k0 + 9) * 128 + m0 + 8], b[3], s[3]);
        g_wfB[layer][id2] = make_float4(__uint_as_float(b[0]), __uint_as_float(b[1]),
                                        __uint_as_float(b[2]), __uint_as_float(b[3]));
        g_wfS[layer][id2] = make_float4(__uint_as_float(s[0]), __uint_as_float(s[1]),
                                        __uint_as_float(s[2]), __uint_as_float(s[3]));
    }

    cnt[t] = 0;
    __syncthreads();
    for (int e = t; e < EE; e += 1024) atomicAdd(&cnt[eb[EE + e]], 1);
    __syncthreads();
    int d = cnt[t];

    int v = d;
#pragma unroll
    for (int off = 1; off < 32; off <<= 1) {
        int u = __shfl_up_sync(0xffffffffu, v, off);
        if (lane >= off) v += u;
    }
    if (lane == 31) wtot[warp] = v;
    __syncthreads();
    if (warp == 0) {
        int wv = wtot[lane];
#pragma unroll
        for (int off = 1; off < 32; off <<= 1) {
            int u = __shfl_up_sync(0xffffffffu, wv, off);
            if (lane >= off) wv += u;
        }
        wtot[lane] = wv;
    }
    __syncthreads();
    int incl = v + (warp > 0 ? wtot[warp - 1] : 0);

    if (t < NN) {
        g_rowptr[g * (NN + 1) + t + 1] = incl;
        cur[t] = incl - d;
        float di = rsqrtf((float)d + 1.0f);
        sdinv[t] = di;
        g_dinv[g * NN + t] = di;
    }
    if (t == 0) g_rowptr[g * (NN + 1)] = 0;
    if (t < C) g_gvec[g * C + t] = 0.0f;
    if (g == 0 && t < C) g_nrepr[t] = 0.0f;
    __syncthreads();
    for (int e = t; e < EE; e += 1024) {
        int src = eb[e];
        int dst = eb[EE + e];
        int pos = atomicAdd(&cur[dst], 1);
        g_edge[g * EE + pos] = make_float2(__int_as_float(src), sdinv[src] * sdinv[dst]);
    }
}

// ---------------- bf16x3 tensor-core GEMM: (64000 x 128) @ (128 x 128), fp16 out ----------------
// X packed per (row, q, slot): float4 {blo(pair tig), slo(pair tig), bhi(pair tig+4), shi(pair tig+4)}
// Row stride 36 float4 (144 words). Slot swizzle (tig + (q>>1)) & 3.
// Staging: lane = float4-column (coalesced LDG.128), each thread emits 2 pairs as STS.64.
// Epilogue: D staged in smem (stride 132 floats) -> pack f16x2 -> coalesced STG.
#define XROW_F4 36
#define DROW_F 132
#define GEMM_SMEM_BYTES (64 * XROW_F4 * 16)   // 36864 >= 64*132*4 = 33792

__global__ void __launch_bounds__(256, 3)
gemm_tc_kernel(const float* __restrict__ X,
               const float4* __restrict__ WfB, const float4* __restrict__ WfS,
               __half* __restrict__ Y) {
    extern __shared__ uint32_t usm[];
    float4* Xq4 = (float4*)usm;

    int tid = threadIdx.x;
    int warp = tid >> 5, lane = tid & 31;
    int rowBase = blockIdx.x * 64;

    // ---- staging: lane = c4 (coalesced LDG.128), pair-local STS.64 (conflict-free)
    {
        int c4 = lane;                   // float4 column 0..31
        int q = c4 >> 2;                 // k16 chunk
        int l2 = c4 & 3;                 // pair group: pairs 2*l2, 2*l2+1 of chunk q
#pragma unroll
        for (int it = 0; it < 8; it++) {
            int r = it * 8 + warp;
            float4 v = ((const float4*)(X + (size_t)(rowBase + r) * C))[c4];
#pragma unroll
            for (int p = 0; p < 2; p++) {
                int tt = 2 * l2 + p;
                int tg = tt & 3;
                int comp = tt >> 2;                       // 0: words {0,1}, 1: words {2,3}
                int slot = (tg + (q >> 1)) & 3;
                uint32_t big, small;
                if (p == 0) split2bf(v.x, v.y, big, small);
                else        split2bf(v.z, v.w, big, small);
                uint32_t* w = usm + r * (XROW_F4 * 4) + q * 16 + slot * 4 + comp * 2;
                *(uint2*)w = make_uint2(big, small);      // STS.64
            }
        }
    }
    __syncthreads();

    int grp = lane >> 2, tig = lane & 3;
    int wN = warp & 3, wM = warp >> 2;      // 4 N-groups x 2 M-groups
    int ct0 = wN * 2;                       // two 16-col tiles per warp
    int rbase = wM * 32;                    // 32 rows per warp (4 rt of 8)

    float d[2][4][4];
#pragma unroll
    for (int a = 0; a < 2; a++)
#pragma unroll
        for (int b = 0; b < 4; b++)
#pragma unroll
            for (int c = 0; c < 4; c++) d[a][b][c] = 0.0f;

    const float4* wb0 = WfB + ct0 * 256 + lane;
    const float4* ws0 = WfS + ct0 * 256 + lane;
    const float4* wb1 = WfB + (ct0 + 1) * 256 + lane;
    const float4* ws1 = WfS + (ct0 + 1) * 256 + lane;

#pragma unroll
    for (int q = 0; q < 8; q++) {
        float4 A0 = __ldg(wb0 + q * 32);
        float4 S0 = __ldg(ws0 + q * 32);
        float4 A1 = __ldg(wb1 + q * 32);
        float4 S1 = __ldg(ws1 + q * 32);
        uint32_t a00 = __float_as_uint(A0.x), a01 = __float_as_uint(A0.y),
                 a02 = __float_as_uint(A0.z), a03 = __float_as_uint(A0.w);
        uint32_t s00 = __float_as_uint(S0.x), s01 = __float_as_uint(S0.y),
                 s02 = __float_as_uint(S0.z), s03 = __float_as_uint(S0.w);
        uint32_t a10 = __float_as_uint(A1.x), a11 = __float_as_uint(A1.y),
                 a12 = __float_as_uint(A1.z), a13 = __float_as_uint(A1.w);
        uint32_t s10 = __float_as_uint(S1.x), s11 = __float_as_uint(S1.y),
                 s12 = __float_as_uint(S1.z), s13 = __float_as_uint(S1.w);
        int slot = (tig + (q >> 1)) & 3;
#pragma unroll
        for (int rt = 0; rt < 4; rt++) {
            float4 xq = Xq4[(rbase + rt * 8 + grp) * XROW_F4 + q * 4 + slot];
            // layout {blo, slo, bhi, shi}: big = (x, z), small = (y, w)
            uint32_t bb0 = __float_as_uint(xq.x), bb1 = __float_as_uint(xq.z);
            uint32_t bs0 = __float_as_uint(xq.y), bs1 = __float_as_uint(xq.w);
            MMA_BF16(d[0][rt], a00, a01, a02, a03, bb0, bb1);
            MMA_BF16(d[0][rt], s00, s01, s02, s03, bb0, bb1);
            MMA_BF16(d[0][rt], a00, a01, a02, a03, bs0, bs1);
            MMA_BF16(d[1][rt], a10, a11, a12, a13, bb0, bb1);
            MMA_BF16(d[1][rt], s10, s11, s12, s13, bb0, bb1);
            MMA_BF16(d[1][rt], a10, a11, a12, a13, bs0, bs1);
        }
    }

    // ---- epilogue: stage D in smem (conflict-free STS.32), pack fp16, coalesced STG
    __syncthreads();                       // X data no longer needed
    float* Ds = (float*)usm;               // [64][132]
#pragma unroll
    for (int ct = 0; ct < 2; ct++) {
        int cc = (ct0 + ct) * 16 + grp;
#pragma unroll
        for (int rt = 0; rt < 4; rt++) {
            int r0 = rbase + rt * 8 + 2 * tig;
            Ds[r0 * DROW_F + cc]           = d[ct][rt][0];
            Ds[(r0 + 1) * DROW_F + cc]     = d[ct][rt][1];
            Ds[r0 * DROW_F + cc + 8]       = d[ct][rt][2];
            Ds[(r0 + 1) * DROW_F + cc + 8] = d[ct][rt][3];
        }
    }
    __syncthreads();
    for (int i = tid; i < 64 * 64; i += 256) {
        int r = i >> 6, w = i & 63;                      // w = f16x2 word (cols 2w, 2w+1)
        float2 v = *(const float2*)(Ds + r * DROW_F + 2 * w);
        ((uint32_t*)(Y + (size_t)(rowBase + r) * C))[w] = pack2h(v.x, v.y);
    }
}

// ---------------- aggregation: warp per node, lane = 4 cols, fp16 gather ----------------
__device__ __forceinline__ float fast_tanh(float x) {
    float r;
    asm("tanh.approx.f32 %0, %1;" : "=f"(r) : "f"(x));
    return r;
}

template <int LAYER>
__global__ void __launch_bounds__(256)
agg_kernel(const __half* __restrict__ h, float* __restrict__ out,
           const float* __restrict__ bias) {
    int g = blockIdx.y;
    int warp = threadIdx.x >> 5, lane = threadIdx.x & 31;
    int n = blockIdx.x * 8 + warp;      // 0..999
    int col = lane * 4;

    const uint2* hb = (const uint2*)(h + (size_t)g * NN * C);   // row = 32 uint2
    const float2* ep = g_edge + g * EE;
    int st = __ldg(&g_rowptr[g * (NN + 1) + n]);
    int en = __ldg(&g_rowptr[g * (NN + 1) + n + 1]);
    float dn = __ldg(&g_dinv[g * NN + n]);
    float4 bia = *(const float4*)(bias + col);

    float4 self = unpack4h(hb[n * 32 + lane]);
    float d2 = dn * dn;
    float4 acc;
    acc.x = self.x * d2 + bia.x;
    acc.y = self.y * d2 + bia.y;
    acc.z = self.z * d2 + bia.z;
    acc.w = self.w * d2 + bia.w;

    for (int e = st; e < en; e++) {
        float2 eg = __ldg(&ep[e]);
        int s = __float_as_int(eg.x);
        float w = eg.y;
        float4 hr = unpack4h(__ldg(&hb[s * 32 + lane]));
        acc.x += hr.x * w;
        acc.y += hr.y * w;
        acc.z += hr.z * w;
        acc.w += hr.w * w;
    }
    acc.x = fast_tanh(acc.x);
    acc.y = fast_tanh(acc.y);
    acc.z = fast_tanh(acc.z);
    acc.w = fast_tanh(acc.w);

    if (LAYER == 0) {
        *(float4*)(out + ((size_t)g * NN + n) * C + col) = acc;
    } else {
        __shared__ float4 wsum[8][32];
        wsum[warp][lane] = acc;
        __syncthreads();
        if (warp == 0) {
            float4 s = wsum[0][lane];
#pragma unroll
            for (int w = 1; w < 8; w++) {
                float4 t = wsum[w][lane];
                s.x += t.x; s.y += t.y; s.z += t.z; s.w += t.w;
            }
            atomicAdd(&g_gvec[g * C + col], s.x);
            atomicAdd(&g_gvec[g * C + col + 1], s.y);
            atomicAdd(&g_gvec[g * C + col + 2], s.z);
            atomicAdd(&g_gvec[g * C + col + 3], s.w);
        }
    }
}

// ---------------- qkv: one block per graph-row ----------------
__global__ void qkv_kernel(const float* __restrict__ in_w, const float* __restrict__ in_b) {
    int bi = blockIdx.x;
    int tid = threadIdx.x;       // 384 threads
    __shared__ float gr[C];
    if (tid < C) gr[tid] = g_gvec[bi * C + tid];
    __syncthreads();
    float acc = in_b[tid];
    const float* wr = in_w + (size_t)tid * C;
#pragma unroll 4
    for (int c = 0; c < C; c++) acc += gr[c] * wr[c];
    g_qkv[bi * 3 * C + tid] = acc;
}

// ---------------- attention + out-proj + MLP + LN + relu-sum ----------------
__device__ __forceinline__ float blksum128(float v, float* red) {
#pragma unroll
    for (int o = 16; o > 0; o >>= 1) v += __shfl_down_sync(0xffffffffu, v, o);
    if ((threadIdx.x & 31) == 0) red[threadIdx.x >> 5] = v;
    __syncthreads();
    float s = red[0] + red[1] + red[2] + red[3];
    __syncthreads();
    return s;
}

__global__ void tail_kernel(const float* __restrict__ out_w, const float* __restrict__ out_b,
                            const float* __restrict__ ln_g, const float* __restrict__ ln_b,
                            const float* __restrict__ mw1, const float* __restrict__ mb1,
                            const float* __restrict__ mw2, const float* __restrict__ mb2) {
    int bi = blockIdx.x;
    int tid = threadIdx.x;       // 128 threads
    __shared__ float kv[64 * C];
    __shared__ float qrow[C], sc[4 * 64], orow[C], o2row[C], hid[HIDN];
    __shared__ float red[4];

    for (int i = tid; i < 64 * C; i += 128) {
        int r = i >> 7, c = i & 127;
        kv[i] = g_qkv[r * 3 * C + C + c];
    }
    qrow[tid] = g_qkv[bi * 3 * C + tid];
    __syncthreads();

    for (int s = tid; s < 256; s += 128) {
        int h = s >> 6, k = s & 63;
        const float* kr = kv + k * C + h * 32;
        const float* qr = qrow + h * 32;
        float a = 0.f;
#pragma unroll
        for (int dd = 0; dd < 32; dd++) a += qr[dd] * kr[dd];
        sc[s] = a * 0.17677669529663687f;
    }
    __syncthreads();

    if (tid < 4) {
        float m = -1e30f;
        for (int k = 0; k < 64; k++) m = fmaxf(m, sc[tid * 64 + k]);
        float ssum = 0.f;
        for (int k = 0; k < 64; k++) { float e = expf(sc[tid * 64 + k] - m); sc[tid * 64 + k] = e; ssum += e; }
        float inv = 1.0f / ssum;
        for (int k = 0; k < 64; k++) sc[tid * 64 + k] *= inv;
    }
    __syncthreads();

    for (int i = tid; i < 64 * C; i += 128) {
        int r = i >> 7, c = i & 127;
        kv[i] = g_qkv[r * 3 * C + 2 * C + c];
    }
    __syncthreads();

    {
        int c = tid, h = c >> 5;
        float a = 0.f;
        for (int k = 0; k < 64; k++) a += sc[h * 64 + k] * kv[k * C + c];
        orow[c] = a;
    }
    __syncthreads();

    {
        int j = tid;
        float a = out_b[j];
        const float* wr = out_w + (size_t)j * C;
#pragma unroll 4
        for (int c = 0; c < C; c++) a += orow[c] * wr[c];
        o2row[j] = a;
    }
    __syncthreads();

    for (int j = tid; j < HIDN; j += 128) {
        float a = mb1[j];
        for (int c = 0; c < C; c++) a += o2row[c] * mw1[c * HIDN + j];
        hid[j] = fmaxf(a, 0.f);
    }
    __syncthreads();

    float y;
    {
        int c = tid;
        float a = mb2[c];
        for (int j = 0; j < HIDN; j++) a += hid[j] * mw2[j * C + c];
        y = o2row[c] + a;
    }
    float mu = blksum128(y, red) * (1.0f / 128.0f);
    float d = y - mu;
    float var = blksum128(d * d, red) * (1.0f / 128.0f);
    float yn = d * rsqrtf(var + 1e-5f) * ln_g[tid] + ln_b[tid];
    atomicAdd(&g_nrepr[tid], fmaxf(yn, 0.f));
}

__global__ void final_kernel(const float* __restrict__ lw, const float* __restrict__ lb,
                             float* __restrict__ out) {
    int tid = threadIdx.x;
    if (tid < NCLS) {
        float a = lb[tid];
        for (int c = 0; c < C; c++) a += g_nrepr[c] * lw[c * NCLS + tid];
        out[tid] = a;
    }
}

// ---------------- launch ----------------
extern "C" void kernel_launch(void* const* d_in, const int* in_sizes, int n_in,
                              void* d_out, int out_size) {
    const float* x     = (const float*)d_in[0];
    const int*   ei    = (const int*)d_in[1];
    const float* W0    = (const float*)d_in[2];
    const float* b0    = (const float*)d_in[3];
    const float* W1    = (const float*)d_in[4];
    const float* b1    = (const float*)d_in[5];
    const float* in_w  = (const float*)d_in[6];
    const float* in_b  = (const float*)d_in[7];
    const float* out_w = (const float*)d_in[8];
    const float* out_b = (const float*)d_in[9];
    const float* ln2_g = (const float*)d_in[10];
    const float* ln2_b = (const float*)d_in[11];
    const float* mw1   = (const float*)d_in[12];
    const float* mb1   = (const float*)d_in[13];
    const float* mw2   = (const float*)d_in[14];
    const float* mb2   = (const float*)d_in[15];
    const float* lw    = (const float*)d_in[16];
    const float* lb    = (const float*)d_in[17];
    float* out = (float*)d_out;

    __half* bufA;
    float* bufB;
    cudaGetSymbolAddress((void**)&bufA, g_bufA);
    cudaGetSymbolAddress((void**)&bufB, g_bufB);
    float4 *wfB, *wfS;
    cudaGetSymbolAddress((void**)&wfB, g_wfB);
    cudaGetSymbolAddress((void**)&wfS, g_wfS);

    cudaFuncSetAttribute(gemm_tc_kernel, cudaFuncAttributeMaxDynamicSharedMemorySize, GEMM_SMEM_BYTES);

    prep_kernel<<<G, 1024>>>(ei, W0, W1);

    gemm_tc_kernel<<<(G * NN) / 64, 256, GEMM_SMEM_BYTES>>>(x, wfB, wfS, bufA);
    agg_kernel<0><<<dim3(125, G), 256>>>(bufA, bufB, b0);
    gemm_tc_kernel<<<(G * NN) / 64, 256, GEMM_SMEM_BYTES>>>(bufB, wfB + 2048, wfS + 2048, bufA);
    agg_kernel<1><<<dim3(125, G), 256>>>(bufA, nullptr, b1);

    qkv_kernel<<<G, 3 * C>>>(in_w, in_b);
    tail_kernel<<<G, C>>>(out_w, out_b, ln2_g, ln2_b, mw1, mb1, mw2, mb2);
    final_kernel<<<1, 32>>>(lw, lb, out);
}